// round 6
// baseline (speedup 1.0000x reference)
#include <cuda_runtime.h>

#define B_SZ    256
#define NDATA   200000
#define BITW    64
#define TOPF    20
#define KNEG    2500
#define RANK_KTH 20000          /* N - HIGH : ascending 0-indexed rank of kth   */
#define RANK_TOP 199980         /* N - TOPF : ascending rank of 20th largest    */
#define THRESH  0.3f
#define TVAL    7.2f            /* 0.9*sqrt(64) */
#define PRE_KEY 0.975f
#define NBINS   4096
#define HCHUNK  25000
#define BUFK_CAP 16384
#define BUFT_CAP 8192
#define NEG_CAP  8192

/* ------------- static device scratch (no runtime allocation) ------------- */
__device__ __align__(16) float g_sim[(size_t)B_SZ * NDATA];
__device__ __align__(16) float g_fsum[B_SZ * BITW];
__device__ __align__(16) float g_f1[B_SZ * BITW];
__device__ __align__(16) float g_newf[B_SZ * BITW];
__device__ unsigned int g_hist[B_SZ * NBINS];
__device__ int          g_binK[B_SZ], g_resK[B_SZ], g_binT[B_SZ];
__device__ unsigned int g_kthu[B_SZ];
__device__ unsigned int g_bufK[B_SZ * BUFK_CAP];
__device__ float        g_bufTv[B_SZ * BUFT_CAP];
__device__ int          g_bufTj[B_SZ * BUFT_CAP];
__device__ unsigned int g_negKey[B_SZ * NEG_CAP];
__device__ int          g_negJ[B_SZ * NEG_CAP];
__device__ int          g_cntK[B_SZ], g_cntT[B_SZ], g_cntNeg[B_SZ];
__device__ unsigned long long g_negK2[(size_t)B_SZ * NEG_CAP];
__device__ int          g_topi[B_SZ * TOPF];
__device__ float        g_topv[B_SZ * TOPF];
__device__ float        g_loss[B_SZ];

/* float -> order-preserving uint */
__device__ __forceinline__ unsigned int f2u(float f) {
    unsigned int u = __float_as_uint(f);
    return (u & 0x80000000u) ? ~u : (u | 0x80000000u);
}
__device__ __forceinline__ float u2f(unsigned int x) {
    unsigned int u = (x & 0x80000000u) ? (x ^ 0x80000000u) : ~x;
    return __uint_as_float(u);
}

/* ------------------------- K0: zero counters/hist ------------------------- */
__global__ void k_zero() {
    int i = blockIdx.x * blockDim.x + threadIdx.x;
    int stride = gridDim.x * blockDim.x;
    for (int x = i; x < B_SZ * NBINS; x += stride) g_hist[x] = 0u;
    if (i < B_SZ) { g_cntK[i] = 0; g_cntT[i] = 0; g_cntNeg[i] = 0; }
}

/* --------------- K1: fusions, norms, fsum, f1, new_feature --------------- */
__global__ void k_prep(const float* __restrict__ iA, const float* __restrict__ iB,
                       const float* __restrict__ tA, const float* __restrict__ tB) {
    int b = blockIdx.x, k = threadIdx.x;               /* 64 threads */
    float ia = iA[b * BITW + k], ib = iB[b * BITW + k];
    float ta = tA[b * BITW + k], tb = tB[b * BITW + k];
    float f1 = (ia + ta) * 0.5f, f2 = (ia + tb) * 0.5f;
    float f3 = (ib + ta) * 0.5f, f4 = (ib + tb) * 0.5f;
    __shared__ float s[4][BITW];
    __shared__ float n[4];
    s[0][k] = f1 * f1; s[1][k] = f2 * f2; s[2][k] = f3 * f3; s[3][k] = f4 * f4;
    __syncthreads();
    if (k < 4) { float t = 0.f; for (int i = 0; i < BITW; i++) t += s[k][i]; n[k] = sqrtf(t); }
    __syncthreads();
    g_fsum[b * BITW + k] = 0.25f * (f1 / n[0] + f2 / n[1] + f3 / n[2] + f4 / n[3]);
    g_f1[b * BITW + k]   = f1;
    g_newf[b * BITW + k] = f1 / n[0];
}

/* -------------- K2: sim = fsum @ memory^T  (packed f32x2 FMA) ------------ */
__global__ void __launch_bounds__(128) k_gemm(const float* __restrict__ memory) {
    __shared__ float s_fsum[128 * BITW];               /* 32 KB */
    int tid = threadIdx.x;
    int j = blockIdx.x * 128 + tid;

    unsigned long long r2[32];
    if (j < NDATA) {
        const ulonglong2* mp = (const ulonglong2*)(memory + (size_t)j * BITW);
#pragma unroll
        for (int q = 0; q < 16; q++) { ulonglong2 t = mp[q]; r2[2*q] = t.x; r2[2*q+1] = t.y; }
    }

    for (int half = 0; half < 2; half++) {
        __syncthreads();
        const float4* fsrc = (const float4*)(g_fsum + half * 128 * BITW);
        float4* fdst = (float4*)s_fsum;
        for (int i = tid; i < 128 * BITW / 4; i += 128) fdst[i] = fsrc[i];
        __syncthreads();
        if (j < NDATA) {
#pragma unroll 1
            for (int b = 0; b < 128; b++) {
                const unsigned long long* fp = (const unsigned long long*)(s_fsum + b * BITW);
                unsigned long long a0 = 0ull, a1 = 0ull, a2 = 0ull, a3 = 0ull;
#pragma unroll
                for (int q = 0; q < 8; q++) {
                    asm("fma.rn.f32x2 %0, %1, %2, %0;" : "+l"(a0) : "l"(r2[4*q+0]), "l"(fp[4*q+0]));
                    asm("fma.rn.f32x2 %0, %1, %2, %0;" : "+l"(a1) : "l"(r2[4*q+1]), "l"(fp[4*q+1]));
                    asm("fma.rn.f32x2 %0, %1, %2, %0;" : "+l"(a2) : "l"(r2[4*q+2]), "l"(fp[4*q+2]));
                    asm("fma.rn.f32x2 %0, %1, %2, %0;" : "+l"(a3) : "l"(r2[4*q+3]), "l"(fp[4*q+3]));
                }
                float v = (__uint_as_float((unsigned)a0) + __uint_as_float((unsigned)(a0 >> 32)))
                        + (__uint_as_float((unsigned)a1) + __uint_as_float((unsigned)(a1 >> 32)))
                        + (__uint_as_float((unsigned)a2) + __uint_as_float((unsigned)(a2 >> 32)))
                        + (__uint_as_float((unsigned)a3) + __uint_as_float((unsigned)(a3 >> 32)));
                g_sim[(size_t)(half * 128 + b) * NDATA + j] = v;
            }
        }
    }
}

/* --------------- K3: per-sample 4096-bin histogram of sim ---------------- */
__global__ void k_hist() {
    __shared__ unsigned int sh[NBINS];
    int b = blockIdx.y, tid = threadIdx.x;             /* 256 threads */
    for (int i = tid; i < NBINS; i += 256) sh[i] = 0u;
    __syncthreads();
    size_t base = (size_t)b * NDATA;
    int j0 = blockIdx.x * HCHUNK;
    for (int j = j0 + tid * 4; j < j0 + HCHUNK; j += 256 * 4) {
        float4 s4 = *(const float4*)&g_sim[base + j];
        atomicAdd(&sh[f2u(s4.x) >> 20], 1u);
        atomicAdd(&sh[f2u(s4.y) >> 20], 1u);
        atomicAdd(&sh[f2u(s4.z) >> 20], 1u);
        atomicAdd(&sh[f2u(s4.w) >> 20], 1u);
    }
    __syncthreads();
    for (int i = tid; i < NBINS; i += 256) {
        unsigned int c = sh[i];
        if (c) atomicAdd(&g_hist[b * NBINS + i], c);
    }
}

/* --------- K4: prefix over bins; find bins holding the two ranks --------- */
__global__ void k_scan() {
    int b = blockIdx.x, tid = threadIdx.x;             /* 256 threads x 16 bins */
    __shared__ unsigned int part[256], pref[256];
    unsigned int s = 0;
    for (int i = 0; i < 16; i++) s += g_hist[b * NBINS + tid * 16 + i];
    part[tid] = s;
    __syncthreads();
    if (tid == 0) { unsigned int c = 0; for (int i = 0; i < 256; i++) { pref[i] = c; c += part[i]; } }
    __syncthreads();
    unsigned int c = pref[tid];
    for (int i = 0; i < 16; i++) {
        unsigned int cnt = g_hist[b * NBINS + tid * 16 + i];
        unsigned int nc = c + cnt;
        if (c <= (unsigned)RANK_KTH && (unsigned)RANK_KTH < nc) {
            g_binK[b] = tid * 16 + i; g_resK[b] = RANK_KTH - (int)c;
        }
        if (c <= (unsigned)RANK_TOP && (unsigned)RANK_TOP < nc) g_binT[b] = tid * 16 + i;
        c = nc;
    }
}

/* -------- K5: compact boundary bin, top tail, prefiltered neg keys ------- */
__global__ void k_compact(const float* __restrict__ ru) {
    int b = blockIdx.y;
    int binK = g_binK[b], binT = g_binT[b];
    size_t base = (size_t)b * NDATA;
    int j0 = blockIdx.x * HCHUNK;
    for (int j = j0 + threadIdx.x * 4; j < j0 + HCHUNK; j += 256 * 4) {
        float4 s4 = *(const float4*)&g_sim[base + j];
        float4 r4 = *(const float4*)&ru[base + j];
        float sv[4] = {s4.x, s4.y, s4.z, s4.w};
        float rv[4] = {r4.x, r4.y, r4.z, r4.w};
#pragma unroll
        for (int t = 0; t < 4; t++) {
            unsigned int u = f2u(sv[t]);
            int bin = (int)(u >> 20);
            if (bin >= binK) {
                if (bin == binK) {
                    int id = atomicAdd(&g_cntK[b], 1);
                    if (id < BUFK_CAP) g_bufK[b * BUFK_CAP + id] = u;
                }
                if (bin >= binT) {
                    int id = atomicAdd(&g_cntT[b], 1);
                    if (id < BUFT_CAP) { g_bufTv[b * BUFT_CAP + id] = sv[t]; g_bufTj[b * BUFT_CAP + id] = j + t; }
                }
            }
            if (rv[t] >= PRE_KEY) {
                int id = atomicAdd(&g_cntNeg[b], 1);
                if (id < NEG_CAP) {
                    g_negKey[b * NEG_CAP + id] = __float_as_uint(rv[t]);
                    g_negJ[b * NEG_CAP + id] = j + t;
                }
            }
        }
    }
}

/* -------------- K6: exact kth value via 4-bit radix refine --------------- */
__global__ void k_selectK() {
    int b = blockIdx.x, tid = threadIdx.x;             /* 256 threads */
    __shared__ int h16[16];
    __shared__ unsigned s_pref;
    __shared__ int s_rank;
    int n = min(g_cntK[b], BUFK_CAP);
    if (tid == 0) { s_pref = (unsigned)g_binK[b] << 20; s_rank = g_resK[b]; }
    __syncthreads();
    unsigned pmask = 0xFFF00000u;
    for (int shift = 16; shift >= 0; shift -= 4) {
        if (tid < 16) h16[tid] = 0;
        __syncthreads();
        unsigned pref = s_pref;
        for (int i = tid; i < n; i += 256) {
            unsigned u = g_bufK[b * BUFK_CAP + i];
            if ((u & pmask) == pref) atomicAdd(&h16[(u >> shift) & 15], 1);
        }
        __syncthreads();
        if (tid == 0) {
            int r = s_rank, cum = 0, d = 0;
            for (; d < 16; d++) { int c = h16[d]; if (r < cum + c) { s_rank = r - cum; break; } cum += c; }
            s_pref = pref | ((unsigned)d << shift);
        }
        pmask |= (15u << shift);
        __syncthreads();
    }
    if (tid == 0) g_kthu[b] = s_pref;
}

/* ----- K7: exact top-20 (JAX tie order: value desc, index asc) ----------- */
__global__ void k_selectT() {
    int b = blockIdx.x, lane = threadIdx.x;            /* 32 threads */
    int m = min(g_cntT[b], BUFT_CAP);
    unsigned long long prev = 0xFFFFFFFFFFFFFFFFull;
    for (int it = 0; it < TOPF; it++) {
        unsigned long long best = 0ull;
        for (int i = lane; i < m; i += 32) {
            unsigned long long K = ((unsigned long long)f2u(g_bufTv[b * BUFT_CAP + i]) << 32)
                                 | (unsigned)(~(unsigned)g_bufTj[b * BUFT_CAP + i]);
            if (K < prev && K > best) best = K;
        }
        for (int o = 16; o; o >>= 1) {
            unsigned long long other = __shfl_down_sync(0xffffffffu, best, o);
            if (other > best) best = other;
        }
        best = __shfl_sync(0xffffffffu, best, 0);
        if (lane == 0) {
            g_topv[b * TOPF + it] = u2f((unsigned)(best >> 32));
            g_topi[b * TOPF + it] = (int)(~((unsigned)(best & 0xffffffffu)));
        }
        prev = best;
    }
}

/* ---- K8: filter negs, exact 2500-th key theta, Sum exp, fnp/pos, loss --- */
__global__ void k_neg(const float* __restrict__ memory, const int* __restrict__ bidx) {
    int b = blockIdx.x, tid = threadIdx.x;             /* 256 threads */
    __shared__ float s_f1[BITW];
    __shared__ int s_topi[TOPF], s_valid[TOPF];
    __shared__ float s_topv[TOPF];
    __shared__ int s_pos, s_m2, s_rank, h16[16];
    __shared__ unsigned s_kthu;
    __shared__ unsigned long long s_pref;
    __shared__ float red[256];

    if (tid < BITW) s_f1[tid] = g_f1[b * BITW + tid];
    if (tid == 0) { s_pos = bidx[b]; s_kthu = g_kthu[b]; s_m2 = 0; }
    if (tid < TOPF) { s_topi[tid] = g_topi[b * TOPF + tid]; s_topv[tid] = g_topv[b * TOPF + tid]; }
    __syncthreads();
    if (tid < TOPF) s_valid[tid] = (s_topv[tid] > THRESH && s_topi[tid] != s_pos) ? 1 : 0;
    __syncthreads();
    int pos = s_pos;
    unsigned kthu = s_kthu;

    /* filter + compact surviving 64-bit keys */
    int m = min(g_cntNeg[b], NEG_CAP);
    unsigned long long* K2 = &g_negK2[(size_t)b * NEG_CAP];
    for (int i = tid; i < m; i += 256) {
        int j = g_negJ[b * NEG_CAP + i];
        unsigned keyu = g_negKey[b * NEG_CAP + i];
        if (f2u(g_sim[(size_t)b * NDATA + j]) < kthu) continue;
        if (j == pos) continue;
        bool ex = false;
#pragma unroll
        for (int t = 0; t < TOPF; t++) if (s_valid[t] && s_topi[t] == j) ex = true;
        if (ex) continue;
        int id = atomicAdd(&s_m2, 1);
        K2[id] = ((unsigned long long)keyu << 32) | (unsigned)(~(unsigned)j);
    }
    __syncthreads();
    int m2 = s_m2;

    /* radix-select theta = ascending rank (m2 - KNEG)  == 2500th largest key */
    if (tid == 0) { s_rank = m2 - KNEG; s_pref = 0ull; }
    __syncthreads();
    unsigned long long pmask = 0ull;
    for (int shift = 60; shift >= 0; shift -= 4) {
        if (tid < 16) h16[tid] = 0;
        __syncthreads();
        unsigned long long pref = s_pref;
        for (int i = tid; i < m2; i += 256) {
            unsigned long long K = K2[i];
            if ((K & pmask) == pref) atomicAdd(&h16[(int)((K >> shift) & 15)], 1);
        }
        __syncthreads();
        if (tid == 0) {
            int r = s_rank, cum = 0, d = 0;
            for (; d < 16; d++) { int c = h16[d]; if (r < cum + c) { s_rank = r - cum; break; } cum += c; }
            s_pref = pref | ((unsigned long long)d << shift);
        }
        pmask |= (15ull << shift);
        __syncthreads();
    }
    unsigned long long theta = s_pref;

    /* sum exp(sign(memory[j]) . f1 / T) over selected negatives */
    float acc = 0.f;
    const float scale = 8.0f / TVAL;
    for (int i = tid; i < m2; i += 256) {
        unsigned long long K = K2[i];
        if (K >= theta) {
            int j = (int)(~((unsigned)(K & 0xffffffffu)));
            const float4* mp = (const float4*)(memory + (size_t)j * BITW);
            float d = 0.f;
#pragma unroll
            for (int q = 0; q < 16; q++) {
                float4 t = mp[q];
                d += t.x * s_f1[4*q] + t.y * s_f1[4*q+1] + t.z * s_f1[4*q+2] + t.w * s_f1[4*q+3];
            }
            acc += expf(d * scale);
        }
    }
    red[tid] = acc;
    __syncthreads();
    for (int s = 128; s > 0; s >>= 1) { if (tid < s) red[tid] += red[tid + s]; __syncthreads(); }

    if (tid == 0) {
        float negsum = red[0];
        const float* mpos = memory + (size_t)pos * BITW;
        float dp = 0.f;
        for (int q = 0; q < BITW; q++) dp += mpos[q] * s_f1[q];
        float pos_sim = dp * scale;
        float pe = expf(pos_sim);
        float numer = pe, nf = 0.f;
        for (int t = 0; t < TOPF; t++) {
            if (s_valid[t]) {
                const float* mr = memory + (size_t)s_topi[t] * BITW;
                float d = 0.f;
                for (int q = 0; q < BITW; q++) d += mr[q] * s_f1[q];
                float fs = d * scale;
                numer += fs * expf(fs);
                nf += 1.f;
            }
        }
        float den = negsum + pe;
        g_loss[b] = -logf(numer / den) / (1.f + nf);
    }
}

/* ---- K9: memory -> out copy (dst is out+1: 4B-aligned, scalar stores) --- */
__global__ void k_copy(const float* __restrict__ memory, float* __restrict__ outmem) {
    int n4 = NDATA * BITW / 4;
    int stride = gridDim.x * blockDim.x;
    for (int i = blockIdx.x * blockDim.x + threadIdx.x; i < n4; i += stride) {
        float4 v = *(const float4*)(memory + (size_t)i * 4);
        size_t o = (size_t)i * 4;
        outmem[o]     = v.x;
        outmem[o + 1] = v.y;
        outmem[o + 2] = v.z;
        outmem[o + 3] = v.w;
    }
}

/* -------- K10: momentum update scatter (last-write-wins on dups) --------- */
__global__ void k_update(const float* __restrict__ memory, const int* __restrict__ bidx,
                         float* __restrict__ outmem) {
    int b = blockIdx.x, k = threadIdx.x;               /* 64 threads */
    __shared__ int skip;
    __shared__ float s[BITW];
    __shared__ float nrm;
    if (k == 0) {
        skip = 0;
        int p = bidx[b];
        for (int bb = b + 1; bb < B_SZ; bb++) if (bidx[bb] == p) { skip = 1; break; }
    }
    __syncthreads();
    if (skip) return;
    int p = bidx[b];
    float v = memory[(size_t)p * BITW + k] * 0.4f + g_newf[b * BITW + k] * 0.6f;
    s[k] = v * v;
    __syncthreads();
    if (k == 0) { float t = 0.f; for (int i = 0; i < BITW; i++) t += s[i]; nrm = sqrtf(t); }
    __syncthreads();
    outmem[(size_t)p * BITW + k] = v / nrm;
}

/* -------------------------- K11: mean loss ------------------------------- */
__global__ void k_loss(float* __restrict__ out) {
    __shared__ float r[256];
    int tid = threadIdx.x;
    r[tid] = g_loss[tid];
    __syncthreads();
    for (int s = 128; s > 0; s >>= 1) { if (tid < s) r[tid] += r[tid + s]; __syncthreads(); }
    if (tid == 0) out[0] = r[0] * (1.0f / B_SZ);
}

/* ------------------------------------------------------------------------- */
extern "C" void kernel_launch(void* const* d_in, const int* in_sizes, int n_in,
                              void* d_out, int out_size) {
    const float* iA     = (const float*)d_in[0];
    const float* iB     = (const float*)d_in[1];
    const float* tA     = (const float*)d_in[2];
    const float* tB     = (const float*)d_in[3];
    const float* memory = (const float*)d_in[4];
    const float* ru     = (const float*)d_in[5];
    const int*   bidx   = (const int*)d_in[6];
    float* out = (float*)d_out;

    k_zero<<<1024, 256>>>();
    k_prep<<<B_SZ, BITW>>>(iA, iB, tA, tB);
    k_gemm<<<(NDATA + 127) / 128, 128>>>(memory);
    k_hist<<<dim3(NDATA / HCHUNK, B_SZ), 256>>>();
    k_scan<<<B_SZ, 256>>>();
    k_compact<<<dim3(NDATA / HCHUNK, B_SZ), 256>>>(ru);
    k_selectK<<<B_SZ, 256>>>();
    k_selectT<<<B_SZ, 32>>>();
    k_neg<<<B_SZ, 256>>>(memory, bidx);
    k_copy<<<2048, 256>>>(memory, out + 1);
    k_update<<<B_SZ, BITW>>>(memory, bidx, out + 1);
    k_loss<<<1, 256>>>(out);
}

// round 10
// speedup vs baseline: 1.0523x; 1.0523x over previous
#include <cuda_runtime.h>
#include <cuda_bf16.h>
#include <cstdint>

#define B_SZ    256
#define NDATA   200000
#define BITW    64
#define TOPF    20
#define KNEG    2500
#define RANK_KTH 20000          /* N - HIGH : ascending 0-indexed rank of kth   */
#define RANK_TOP 199980         /* N - TOPF : ascending rank of 20th largest    */
#define THRESH  0.3f
#define TVAL    7.2f            /* 0.9*sqrt(64) */
#define PRE_KEY 0.975f
#define NBINS   4096
#define HCHUNK  25000
#define BUFK_CAP 16384
#define BUFT_CAP 8192
#define NEG_CAP  8192

/* ------------- static device scratch (no runtime allocation) ------------- */
__device__ __align__(16) float g_sim[(size_t)B_SZ * NDATA];
__device__ __align__(16) float g_fsum[B_SZ * BITW];
__device__ __align__(16) float g_f1[B_SZ * BITW];
__device__ __align__(16) float g_newf[B_SZ * BITW];
__device__ __align__(16) __nv_bfloat16 g_fh[B_SZ * BITW];
__device__ __align__(16) __nv_bfloat16 g_fl[B_SZ * BITW];
__device__ unsigned int g_hist[B_SZ * NBINS];
__device__ int          g_binK[B_SZ], g_resK[B_SZ], g_binT[B_SZ];
__device__ unsigned int g_kthu[B_SZ];
__device__ unsigned int g_bufK[B_SZ * BUFK_CAP];
__device__ float        g_bufTv[B_SZ * BUFT_CAP];
__device__ int          g_bufTj[B_SZ * BUFT_CAP];
__device__ unsigned int g_negKey[B_SZ * NEG_CAP];
__device__ int          g_negJ[B_SZ * NEG_CAP];
__device__ int          g_cntK[B_SZ], g_cntT[B_SZ], g_cntNeg[B_SZ];
__device__ unsigned long long g_negK2[(size_t)B_SZ * NEG_CAP];
__device__ int          g_topi[B_SZ * TOPF];
__device__ float        g_topv[B_SZ * TOPF];
__device__ float        g_loss[B_SZ];

/* float -> order-preserving uint */
__device__ __forceinline__ unsigned int f2u(float f) {
    unsigned int u = __float_as_uint(f);
    return (u & 0x80000000u) ? ~u : (u | 0x80000000u);
}
__device__ __forceinline__ float u2f(unsigned int x) {
    unsigned int u = (x & 0x80000000u) ? (x ^ 0x80000000u) : ~x;
    return __uint_as_float(u);
}

/* ------------------------- K0: zero counters/hist ------------------------- */
__global__ void k_zero() {
    int i = blockIdx.x * blockDim.x + threadIdx.x;
    int stride = gridDim.x * blockDim.x;
    for (int x = i; x < B_SZ * NBINS; x += stride) g_hist[x] = 0u;
    if (i < B_SZ) { g_cntK[i] = 0; g_cntT[i] = 0; g_cntNeg[i] = 0; }
}

/* --------------- K1: fusions, norms, fsum (+bf16 hi/lo), f1 -------------- */
__global__ void k_prep(const float* __restrict__ iA, const float* __restrict__ iB,
                       const float* __restrict__ tA, const float* __restrict__ tB) {
    int b = blockIdx.x, k = threadIdx.x;               /* 64 threads */
    float ia = iA[b * BITW + k], ib = iB[b * BITW + k];
    float ta = tA[b * BITW + k], tb = tB[b * BITW + k];
    float f1 = (ia + ta) * 0.5f, f2 = (ia + tb) * 0.5f;
    float f3 = (ib + ta) * 0.5f, f4 = (ib + tb) * 0.5f;
    __shared__ float s[4][BITW];
    __shared__ float n[4];
    s[0][k] = f1 * f1; s[1][k] = f2 * f2; s[2][k] = f3 * f3; s[3][k] = f4 * f4;
    __syncthreads();
    if (k < 4) { float t = 0.f; for (int i = 0; i < BITW; i++) t += s[k][i]; n[k] = sqrtf(t); }
    __syncthreads();
    float fs = 0.25f * (f1 / n[0] + f2 / n[1] + f3 / n[2] + f4 / n[3]);
    g_fsum[b * BITW + k] = fs;
    __nv_bfloat16 h = __float2bfloat16_rn(fs);
    g_fh[b * BITW + k] = h;
    g_fl[b * BITW + k] = __float2bfloat16_rn(fs - __bfloat162float(h));
    g_f1[b * BITW + k]   = f1;
    g_newf[b * BITW + k] = f1 / n[0];
}

/* ---------- K2: sim = fsum @ memory^T via mma.sync bf16 (hi/lo) ----------
 * CTA: 128 j x 256 b. 8 warps, 16 j each. A = memory bf16 (EXACT: +-1/8).
 * B = fsum hi/lo bf16. C fp32 accum over 4 k-steps x 2 splits.
 * smem: A[128 x 144B] | Bh[256 x 144B] | Bl[256 x 144B] | stage[256 x 132 f32]
 * Row strides chosen for conflict-free fragment LDS / staging STS.          */
#define SA_OFF   0
#define SBH_OFF  18432                      /* 128*144 */
#define SBL_OFF  (18432 + 36864)            /* +256*144 */
#define SC_OFF   (18432 + 36864 + 36864)
#define SMEM_MMA_TOTAL (18432 + 36864 + 36864 + 256 * 132 * 4)  /* 227328 */
#define NJB ((NDATA + 127) / 128)

__device__ __forceinline__ void mma_bf16(float& c0, float& c1, float& c2, float& c3,
                                         uint32_t a0, uint32_t a1, uint32_t a2, uint32_t a3,
                                         uint32_t b0, uint32_t b1) {
    asm volatile("mma.sync.aligned.m16n8k16.row.col.f32.bf16.bf16.f32 "
                 "{%0,%1,%2,%3}, {%4,%5,%6,%7}, {%8,%9}, {%0,%1,%2,%3};"
                 : "+f"(c0), "+f"(c1), "+f"(c2), "+f"(c3)
                 : "r"(a0), "r"(a1), "r"(a2), "r"(a3), "r"(b0), "r"(b1));
}

__global__ void __launch_bounds__(256) k_gemm_mma(const float* __restrict__ memory) {
    extern __shared__ char smem[];
    int tid = threadIdx.x, wid = tid >> 5, t = tid & 31;
    int gid = t >> 2, tq = t & 3;
    int jbase = blockIdx.x * 128;

    /* A: 128 rows x 32 bf16-pairs; convert fp32 -> bf16 (exact for +-1/8) */
    for (int idx = tid; idx < 128 * 32; idx += 256) {
        int row = idx >> 5, pr = idx & 31;
        int j = jbase + row;
        uint32_t pk = 0u;
        if (j < NDATA) {
            float2 v = *(const float2*)(memory + (size_t)j * BITW + pr * 2);
            pk = ((uint32_t)__bfloat16_as_ushort(__float2bfloat16_rn(v.y)) << 16)
               |  (uint32_t)__bfloat16_as_ushort(__float2bfloat16_rn(v.x));
        }
        *(uint32_t*)(smem + SA_OFF + row * 144 + pr * 4) = pk;
    }
    /* B hi/lo: restride 64 bf16 rows -> 144B rows */
    for (int idx = tid; idx < 256 * 32; idx += 256) {
        int b = idx >> 5, pr = idx & 31;
        *(uint32_t*)(smem + SBH_OFF + b * 144 + pr * 4) = ((const uint32_t*)g_fh)[b * 32 + pr];
        *(uint32_t*)(smem + SBL_OFF + b * 144 + pr * 4) = ((const uint32_t*)g_fl)[b * 32 + pr];
    }
    __syncthreads();

    /* A fragments for this warp's 16 j rows (rows wid*16 + gid, +8) */
    uint32_t a[4][4];
    {
        int r0 = wid * 16 + gid;
#pragma unroll
        for (int ks = 0; ks < 4; ks++) {
            int kb = (ks * 16 + tq * 2) * 2;               /* byte offset of k0 */
            a[ks][0] = *(const uint32_t*)(smem + SA_OFF + r0 * 144 + kb);
            a[ks][1] = *(const uint32_t*)(smem + SA_OFF + (r0 + 8) * 144 + kb);
            a[ks][2] = *(const uint32_t*)(smem + SA_OFF + r0 * 144 + kb + 16);
            a[ks][3] = *(const uint32_t*)(smem + SA_OFF + (r0 + 8) * 144 + kb + 16);
        }
    }

    float* stg = (float*)(smem + SC_OFF);                  /* [256 b][132 j] */
    for (int bt = 0; bt < 32; bt++) {
        int bB = bt * 8 + gid;                             /* B-frag column  */
        float c0 = 0.f, c1 = 0.f, c2 = 0.f, c3 = 0.f;
        const char* bh = smem + SBH_OFF + bB * 144;
        const char* bl = smem + SBL_OFF + bB * 144;
#pragma unroll
        for (int ks = 0; ks < 4; ks++) {
            int kb = (ks * 16 + tq * 2) * 2;
            uint32_t b0 = *(const uint32_t*)(bh + kb);
            uint32_t b1 = *(const uint32_t*)(bh + kb + 16);
            mma_bf16(c0, c1, c2, c3, a[ks][0], a[ks][1], a[ks][2], a[ks][3], b0, b1);
            b0 = *(const uint32_t*)(bl + kb);
            b1 = *(const uint32_t*)(bl + kb + 16);
            mma_bf16(c0, c1, c2, c3, a[ks][0], a[ks][1], a[ks][2], a[ks][3], b0, b1);
        }
        int jc = wid * 16 + gid;                           /* C row -> j     */
        int bc = bt * 8 + tq * 2;                          /* C col -> b     */
        stg[bc * 132 + jc]           = c0;
        stg[(bc + 1) * 132 + jc]     = c1;
        stg[bc * 132 + jc + 8]       = c2;
        stg[(bc + 1) * 132 + jc + 8] = c3;
    }
    __syncthreads();

    /* coalesced write-out: 256 b rows x 32 float4 */
    for (int idx = tid; idx < 256 * 32; idx += 256) {
        int b = idx >> 5, jj = idx & 31;
        int j = jbase + jj * 4;
        if (j < NDATA) {
            float4 v = *(const float4*)(stg + b * 132 + jj * 4);
            *(float4*)(g_sim + (size_t)b * NDATA + j) = v;
        }
    }
}

/* --------------- K3: per-sample 4096-bin histogram of sim ---------------- */
__global__ void k_hist() {
    __shared__ unsigned int sh[NBINS];
    int b = blockIdx.y, tid = threadIdx.x;             /* 256 threads */
    for (int i = tid; i < NBINS; i += 256) sh[i] = 0u;
    __syncthreads();
    size_t base = (size_t)b * NDATA;
    int j0 = blockIdx.x * HCHUNK;
    for (int j = j0 + tid * 4; j < j0 + HCHUNK; j += 256 * 4) {
        float4 s4 = *(const float4*)&g_sim[base + j];
        atomicAdd(&sh[f2u(s4.x) >> 20], 1u);
        atomicAdd(&sh[f2u(s4.y) >> 20], 1u);
        atomicAdd(&sh[f2u(s4.z) >> 20], 1u);
        atomicAdd(&sh[f2u(s4.w) >> 20], 1u);
    }
    __syncthreads();
    for (int i = tid; i < NBINS; i += 256) {
        unsigned int c = sh[i];
        if (c) atomicAdd(&g_hist[b * NBINS + i], c);
    }
}

/* --------- K4: prefix over bins; find bins holding the two ranks --------- */
__global__ void k_scan() {
    int b = blockIdx.x, tid = threadIdx.x;             /* 256 threads x 16 bins */
    __shared__ unsigned int part[256], pref[256];
    unsigned int s = 0;
    for (int i = 0; i < 16; i++) s += g_hist[b * NBINS + tid * 16 + i];
    part[tid] = s;
    __syncthreads();
    if (tid == 0) { unsigned int c = 0; for (int i = 0; i < 256; i++) { pref[i] = c; c += part[i]; } }
    __syncthreads();
    unsigned int c = pref[tid];
    for (int i = 0; i < 16; i++) {
        unsigned int cnt = g_hist[b * NBINS + tid * 16 + i];
        unsigned int nc = c + cnt;
        if (c <= (unsigned)RANK_KTH && (unsigned)RANK_KTH < nc) {
            g_binK[b] = tid * 16 + i; g_resK[b] = RANK_KTH - (int)c;
        }
        if (c <= (unsigned)RANK_TOP && (unsigned)RANK_TOP < nc) g_binT[b] = tid * 16 + i;
        c = nc;
    }
}

/* -------- K5: compact boundary bin, top tail, prefiltered neg keys ------- */
__global__ void k_compact(const float* __restrict__ ru) {
    int b = blockIdx.y;
    int binK = g_binK[b], binT = g_binT[b];
    size_t base = (size_t)b * NDATA;
    int j0 = blockIdx.x * HCHUNK;
    for (int j = j0 + threadIdx.x * 4; j < j0 + HCHUNK; j += 256 * 4) {
        float4 s4 = *(const float4*)&g_sim[base + j];
        float4 r4 = *(const float4*)&ru[base + j];
        float sv[4] = {s4.x, s4.y, s4.z, s4.w};
        float rv[4] = {r4.x, r4.y, r4.z, r4.w};
#pragma unroll
        for (int t = 0; t < 4; t++) {
            unsigned int u = f2u(sv[t]);
            int bin = (int)(u >> 20);
            if (bin >= binK) {
                if (bin == binK) {
                    int id = atomicAdd(&g_cntK[b], 1);
                    if (id < BUFK_CAP) g_bufK[b * BUFK_CAP + id] = u;
                }
                if (bin >= binT) {
                    int id = atomicAdd(&g_cntT[b], 1);
                    if (id < BUFT_CAP) { g_bufTv[b * BUFT_CAP + id] = sv[t]; g_bufTj[b * BUFT_CAP + id] = j + t; }
                }
            }
            if (rv[t] >= PRE_KEY) {
                int id = atomicAdd(&g_cntNeg[b], 1);
                if (id < NEG_CAP) {
                    g_negKey[b * NEG_CAP + id] = __float_as_uint(rv[t]);
                    g_negJ[b * NEG_CAP + id] = j + t;
                }
            }
        }
    }
}

/* -------------- K6: exact kth value via 4-bit radix refine --------------- */
__global__ void k_selectK() {
    int b = blockIdx.x, tid = threadIdx.x;             /* 256 threads */
    __shared__ int h16[16];
    __shared__ unsigned s_pref;
    __shared__ int s_rank;
    int n = min(g_cntK[b], BUFK_CAP);
    if (tid == 0) { s_pref = (unsigned)g_binK[b] << 20; s_rank = g_resK[b]; }
    __syncthreads();
    unsigned pmask = 0xFFF00000u;
    for (int shift = 16; shift >= 0; shift -= 4) {
        if (tid < 16) h16[tid] = 0;
        __syncthreads();
        unsigned pref = s_pref;
        for (int i = tid; i < n; i += 256) {
            unsigned u = g_bufK[b * BUFK_CAP + i];
            if ((u & pmask) == pref) atomicAdd(&h16[(u >> shift) & 15], 1);
        }
        __syncthreads();
        if (tid == 0) {
            int r = s_rank, cum = 0, d = 0;
            for (; d < 16; d++) { int c = h16[d]; if (r < cum + c) { s_rank = r - cum; break; } cum += c; }
            s_pref = pref | ((unsigned)d << shift);
        }
        pmask |= (15u << shift);
        __syncthreads();
    }
    if (tid == 0) g_kthu[b] = s_pref;
}

/* ----- K7: exact top-20 (JAX tie order: value desc, index asc) ----------- */
__global__ void k_selectT() {
    int b = blockIdx.x, lane = threadIdx.x;            /* 32 threads */
    int m = min(g_cntT[b], BUFT_CAP);
    unsigned long long prev = 0xFFFFFFFFFFFFFFFFull;
    for (int it = 0; it < TOPF; it++) {
        unsigned long long best = 0ull;
        for (int i = lane; i < m; i += 32) {
            unsigned long long K = ((unsigned long long)f2u(g_bufTv[b * BUFT_CAP + i]) << 32)
                                 | (unsigned)(~(unsigned)g_bufTj[b * BUFT_CAP + i]);
            if (K < prev && K > best) best = K;
        }
        for (int o = 16; o; o >>= 1) {
            unsigned long long other = __shfl_down_sync(0xffffffffu, best, o);
            if (other > best) best = other;
        }
        best = __shfl_sync(0xffffffffu, best, 0);
        if (lane == 0) {
            g_topv[b * TOPF + it] = u2f((unsigned)(best >> 32));
            g_topi[b * TOPF + it] = (int)(~((unsigned)(best & 0xffffffffu)));
        }
        prev = best;
    }
}

/* ---- K8: filter negs, exact 2500-th key theta, Sum exp, fnp/pos, loss --- */
__global__ void k_neg(const float* __restrict__ memory, const int* __restrict__ bidx) {
    int b = blockIdx.x, tid = threadIdx.x;             /* 256 threads */
    __shared__ float s_f1[BITW];
    __shared__ int s_topi[TOPF], s_valid[TOPF];
    __shared__ float s_topv[TOPF];
    __shared__ int s_pos, s_m2, s_rank, h16[16];
    __shared__ unsigned s_kthu;
    __shared__ unsigned long long s_pref;
    __shared__ float red[256];

    if (tid < BITW) s_f1[tid] = g_f1[b * BITW + tid];
    if (tid == 0) { s_pos = bidx[b]; s_kthu = g_kthu[b]; s_m2 = 0; }
    if (tid < TOPF) { s_topi[tid] = g_topi[b * TOPF + tid]; s_topv[tid] = g_topv[b * TOPF + tid]; }
    __syncthreads();
    if (tid < TOPF) s_valid[tid] = (s_topv[tid] > THRESH && s_topi[tid] != s_pos) ? 1 : 0;
    __syncthreads();
    int pos = s_pos;
    unsigned kthu = s_kthu;

    /* filter + compact surviving 64-bit keys */
    int m = min(g_cntNeg[b], NEG_CAP);
    unsigned long long* K2 = &g_negK2[(size_t)b * NEG_CAP];
    for (int i = tid; i < m; i += 256) {
        int j = g_negJ[b * NEG_CAP + i];
        unsigned keyu = g_negKey[b * NEG_CAP + i];
        if (f2u(g_sim[(size_t)b * NDATA + j]) < kthu) continue;
        if (j == pos) continue;
        bool ex = false;
#pragma unroll
        for (int t = 0; t < TOPF; t++) if (s_valid[t] && s_topi[t] == j) ex = true;
        if (ex) continue;
        int id = atomicAdd(&s_m2, 1);
        K2[id] = ((unsigned long long)keyu << 32) | (unsigned)(~(unsigned)j);
    }
    __syncthreads();
    int m2 = s_m2;

    /* radix-select theta = ascending rank (m2 - KNEG)  == 2500th largest key */
    if (tid == 0) { s_rank = m2 - KNEG; s_pref = 0ull; }
    __syncthreads();
    unsigned long long pmask = 0ull;
    for (int shift = 60; shift >= 0; shift -= 4) {
        if (tid < 16) h16[tid] = 0;
        __syncthreads();
        unsigned long long pref = s_pref;
        for (int i = tid; i < m2; i += 256) {
            unsigned long long K = K2[i];
            if ((K & pmask) == pref) atomicAdd(&h16[(int)((K >> shift) & 15)], 1);
        }
        __syncthreads();
        if (tid == 0) {
            int r = s_rank, cum = 0, d = 0;
            for (; d < 16; d++) { int c = h16[d]; if (r < cum + c) { s_rank = r - cum; break; } cum += c; }
            s_pref = pref | ((unsigned long long)d << shift);
        }
        pmask |= (15ull << shift);
        __syncthreads();
    }
    unsigned long long theta = s_pref;

    /* sum exp(sign(memory[j]) . f1 / T) over selected negatives */
    float acc = 0.f;
    const float scale = 8.0f / TVAL;
    for (int i = tid; i < m2; i += 256) {
        unsigned long long K = K2[i];
        if (K >= theta) {
            int j = (int)(~((unsigned)(K & 0xffffffffu)));
            const float4* mp = (const float4*)(memory + (size_t)j * BITW);
            float d = 0.f;
#pragma unroll
            for (int q = 0; q < 16; q++) {
                float4 t = mp[q];
                d += t.x * s_f1[4*q] + t.y * s_f1[4*q+1] + t.z * s_f1[4*q+2] + t.w * s_f1[4*q+3];
            }
            acc += expf(d * scale);
        }
    }
    red[tid] = acc;
    __syncthreads();
    for (int s = 128; s > 0; s >>= 1) { if (tid < s) red[tid] += red[tid + s]; __syncthreads(); }

    if (tid == 0) {
        float negsum = red[0];
        const float* mpos = memory + (size_t)pos * BITW;
        float dp = 0.f;
        for (int q = 0; q < BITW; q++) dp += mpos[q] * s_f1[q];
        float pos_sim = dp * scale;
        float pe = expf(pos_sim);
        float numer = pe, nf = 0.f;
        for (int t = 0; t < TOPF; t++) {
            if (s_valid[t]) {
                const float* mr = memory + (size_t)s_topi[t] * BITW;
                float d = 0.f;
                for (int q = 0; q < BITW; q++) d += mr[q] * s_f1[q];
                float fs = d * scale;
                numer += fs * expf(fs);
                nf += 1.f;
            }
        }
        float den = negsum + pe;
        g_loss[b] = -logf(numer / den) / (1.f + nf);
    }
}

/* ---- K9: memory -> out copy (dst is out+1: 4B-aligned, scalar stores) --- */
__global__ void k_copy(const float* __restrict__ memory, float* __restrict__ outmem) {
    int n4 = NDATA * BITW / 4;
    int stride = gridDim.x * blockDim.x;
    for (int i = blockIdx.x * blockDim.x + threadIdx.x; i < n4; i += stride) {
        float4 v = *(const float4*)(memory + (size_t)i * 4);
        size_t o = (size_t)i * 4;
        outmem[o]     = v.x;
        outmem[o + 1] = v.y;
        outmem[o + 2] = v.z;
        outmem[o + 3] = v.w;
    }
}

/* -------- K10: momentum update scatter (last-write-wins on dups) --------- */
__global__ void k_update(const float* __restrict__ memory, const int* __restrict__ bidx,
                         float* __restrict__ outmem) {
    int b = blockIdx.x, k = threadIdx.x;               /* 64 threads */
    __shared__ int skip;
    __shared__ float s[BITW];
    __shared__ float nrm;
    if (k == 0) {
        skip = 0;
        int p = bidx[b];
        for (int bb = b + 1; bb < B_SZ; bb++) if (bidx[bb] == p) { skip = 1; break; }
    }
    __syncthreads();
    if (skip) return;
    int p = bidx[b];
    float v = memory[(size_t)p * BITW + k] * 0.4f + g_newf[b * BITW + k] * 0.6f;
    s[k] = v * v;
    __syncthreads();
    if (k == 0) { float t = 0.f; for (int i = 0; i < BITW; i++) t += s[i]; nrm = sqrtf(t); }
    __syncthreads();
    outmem[(size_t)p * BITW + k] = v / nrm;
}

/* -------------------------- K11: mean loss ------------------------------- */
__global__ void k_loss(float* __restrict__ out) {
    __shared__ float r[256];
    int tid = threadIdx.x;
    r[tid] = g_loss[tid];
    __syncthreads();
    for (int s = 128; s > 0; s >>= 1) { if (tid < s) r[tid] += r[tid + s]; __syncthreads(); }
    if (tid == 0) out[0] = r[0] * (1.0f / B_SZ);
}

/* ------------------------------------------------------------------------- */
extern "C" void kernel_launch(void* const* d_in, const int* in_sizes, int n_in,
                              void* d_out, int out_size) {
    const float* iA     = (const float*)d_in[0];
    const float* iB     = (const float*)d_in[1];
    const float* tA     = (const float*)d_in[2];
    const float* tB     = (const float*)d_in[3];
    const float* memory = (const float*)d_in[4];
    const float* ru     = (const float*)d_in[5];
    const int*   bidx   = (const int*)d_in[6];
    float* out = (float*)d_out;

    cudaFuncSetAttribute(k_gemm_mma, cudaFuncAttributeMaxDynamicSharedMemorySize, SMEM_MMA_TOTAL);

    k_zero<<<1024, 256>>>();
    k_prep<<<B_SZ, BITW>>>(iA, iB, tA, tB);
    k_gemm_mma<<<NJB, 256, SMEM_MMA_TOTAL>>>(memory);
    k_hist<<<dim3(NDATA / HCHUNK, B_SZ), 256>>>();
    k_scan<<<B_SZ, 256>>>();
    k_compact<<<dim3(NDATA / HCHUNK, B_SZ), 256>>>(ru);
    k_selectK<<<B_SZ, 256>>>();
    k_selectT<<<B_SZ, 32>>>();
    k_neg<<<B_SZ, 256>>>(memory, bidx);
    k_copy<<<2048, 256>>>(memory, out + 1);
    k_update<<<B_SZ, BITW>>>(memory, bidx, out + 1);
    k_loss<<<1, 256>>>(out);
}

// round 11
// speedup vs baseline: 1.0995x; 1.0449x over previous
#include <cuda_runtime.h>
#include <cuda_bf16.h>
#include <cstdint>

#define B_SZ    256
#define NDATA   200000
#define BITW    64
#define TOPF    20
#define KNEG    2500
#define RANK_KTH 20000          /* N - HIGH : ascending 0-indexed rank of kth   */
#define RANK_TOP 199980         /* N - TOPF : ascending rank of 20th largest    */
#define THRESH  0.3f
#define TVAL    7.2f            /* 0.9*sqrt(64) */
#define PRE_KEY 0.975f
#define NBINS   4096
#define HCHUNK  25000
#define BUFK_CAP 16384
#define BUFT_CAP 8192
#define NEG_CAP  8192

/* ------------- static device scratch (no runtime allocation) ------------- */
__device__ __align__(16) float g_sim[(size_t)B_SZ * NDATA];
__device__ __align__(16) float g_fsum[B_SZ * BITW];
__device__ __align__(16) float g_f1[B_SZ * BITW];
__device__ __align__(16) float g_newf[B_SZ * BITW];
__device__ __align__(16) __nv_bfloat16 g_fh[B_SZ * BITW];
__device__ __align__(16) __nv_bfloat16 g_fl[B_SZ * BITW];
__device__ unsigned int g_hist[B_SZ * NBINS];
__device__ int          g_binK[B_SZ], g_resK[B_SZ], g_binT[B_SZ];
__device__ unsigned int g_kthu[B_SZ];
__device__ unsigned int g_bufK[B_SZ * BUFK_CAP];
__device__ float        g_bufTv[B_SZ * BUFT_CAP];
__device__ int          g_bufTj[B_SZ * BUFT_CAP];
__device__ unsigned int g_negKey[B_SZ * NEG_CAP];
__device__ int          g_negJ[B_SZ * NEG_CAP];
__device__ int          g_cntK[B_SZ], g_cntT[B_SZ], g_cntNeg[B_SZ];
__device__ unsigned long long g_negK2[(size_t)B_SZ * NEG_CAP];
__device__ int          g_topi[B_SZ * TOPF];
__device__ float        g_topv[B_SZ * TOPF];
__device__ float        g_loss[B_SZ];

/* float -> order-preserving uint */
__device__ __forceinline__ unsigned int f2u(float f) {
    unsigned int u = __float_as_uint(f);
    return (u & 0x80000000u) ? ~u : (u | 0x80000000u);
}
__device__ __forceinline__ float u2f(unsigned int x) {
    unsigned int u = (x & 0x80000000u) ? (x ^ 0x80000000u) : ~x;
    return __uint_as_float(u);
}

/* ------------------------- K0: zero counters/hist ------------------------- */
__global__ void k_zero() {
    int i = blockIdx.x * blockDim.x + threadIdx.x;
    int stride = gridDim.x * blockDim.x;
    for (int x = i; x < B_SZ * NBINS; x += stride) g_hist[x] = 0u;
    if (i < B_SZ) { g_cntK[i] = 0; g_cntT[i] = 0; g_cntNeg[i] = 0; }
}

/* --------------- K1: fusions, norms, fsum (+bf16 hi/lo), f1 -------------- */
__global__ void k_prep(const float* __restrict__ iA, const float* __restrict__ iB,
                       const float* __restrict__ tA, const float* __restrict__ tB) {
    int b = blockIdx.x, k = threadIdx.x;               /* 64 threads */
    float ia = iA[b * BITW + k], ib = iB[b * BITW + k];
    float ta = tA[b * BITW + k], tb = tB[b * BITW + k];
    float f1 = (ia + ta) * 0.5f, f2 = (ia + tb) * 0.5f;
    float f3 = (ib + ta) * 0.5f, f4 = (ib + tb) * 0.5f;
    __shared__ float s[4][BITW];
    __shared__ float n[4];
    s[0][k] = f1 * f1; s[1][k] = f2 * f2; s[2][k] = f3 * f3; s[3][k] = f4 * f4;
    __syncthreads();
    if (k < 4) { float t = 0.f; for (int i = 0; i < BITW; i++) t += s[k][i]; n[k] = sqrtf(t); }
    __syncthreads();
    float fs = 0.25f * (f1 / n[0] + f2 / n[1] + f3 / n[2] + f4 / n[3]);
    g_fsum[b * BITW + k] = fs;
    __nv_bfloat16 h = __float2bfloat16_rn(fs);
    g_fh[b * BITW + k] = h;
    g_fl[b * BITW + k] = __float2bfloat16_rn(fs - __bfloat162float(h));
    g_f1[b * BITW + k]   = f1;
    g_newf[b * BITW + k] = f1 / n[0];
}

/* ---------- K2: sim = fsum @ memory^T via mma.sync bf16 (hi/lo) ----------
 * CTA: 128 j x 256 b. 512 threads / 16 warps: warp w -> j rows (w&7)*16..+15,
 * bt range (w>>3)*16..+15. A = memory bf16 (EXACT: +-1/8). B = fsum hi/lo.
 * smem: A[128 x 144B] | Bh[256 x 144B] | Bl[256 x 144B] | stage[256 x 132 f32]
 * Row strides chosen for conflict-free fragment LDS / staging STS.          */
#define SA_OFF   0
#define SBH_OFF  18432                      /* 128*144 */
#define SBL_OFF  (18432 + 36864)            /* +256*144 */
#define SC_OFF   (18432 + 36864 + 36864)
#define SMEM_MMA_TOTAL (18432 + 36864 + 36864 + 256 * 132 * 4)  /* 227328 */
#define NJB ((NDATA + 127) / 128)
#define GTHREADS 512

__device__ __forceinline__ void mma_bf16(float& c0, float& c1, float& c2, float& c3,
                                         uint32_t a0, uint32_t a1, uint32_t a2, uint32_t a3,
                                         uint32_t b0, uint32_t b1) {
    asm volatile("mma.sync.aligned.m16n8k16.row.col.f32.bf16.bf16.f32 "
                 "{%0,%1,%2,%3}, {%4,%5,%6,%7}, {%8,%9}, {%0,%1,%2,%3};"
                 : "+f"(c0), "+f"(c1), "+f"(c2), "+f"(c3)
                 : "r"(a0), "r"(a1), "r"(a2), "r"(a3), "r"(b0), "r"(b1));
}

__global__ void __launch_bounds__(GTHREADS) k_gemm_mma(const float* __restrict__ memory) {
    extern __shared__ char smem[];
    int tid = threadIdx.x, wid = tid >> 5, t = tid & 31;
    int gid = t >> 2, tq = t & 3;
    int jw = wid & 7, bth = wid >> 3;                  /* j-row set, bt half */
    int jbase = blockIdx.x * 128;

    /* A: 128 rows x 32 bf16-pairs; convert fp32 -> bf16 (exact for +-1/8) */
    for (int idx = tid; idx < 128 * 32; idx += GTHREADS) {
        int row = idx >> 5, pr = idx & 31;
        int j = jbase + row;
        uint32_t pk = 0u;
        if (j < NDATA) {
            float2 v = *(const float2*)(memory + (size_t)j * BITW + pr * 2);
            pk = ((uint32_t)__bfloat16_as_ushort(__float2bfloat16_rn(v.y)) << 16)
               |  (uint32_t)__bfloat16_as_ushort(__float2bfloat16_rn(v.x));
        }
        *(uint32_t*)(smem + SA_OFF + row * 144 + pr * 4) = pk;
    }
    /* B hi/lo: restride 64 bf16 rows -> 144B rows */
    for (int idx = tid; idx < 256 * 32; idx += GTHREADS) {
        int b = idx >> 5, pr = idx & 31;
        *(uint32_t*)(smem + SBH_OFF + b * 144 + pr * 4) = ((const uint32_t*)g_fh)[b * 32 + pr];
        *(uint32_t*)(smem + SBL_OFF + b * 144 + pr * 4) = ((const uint32_t*)g_fl)[b * 32 + pr];
    }
    __syncthreads();

    /* A fragments for this warp's 16 j rows (rows jw*16 + gid, +8) */
    uint32_t a[4][4];
    {
        int r0 = jw * 16 + gid;
#pragma unroll
        for (int ks = 0; ks < 4; ks++) {
            int kb = (ks * 16 + tq * 2) * 2;               /* byte offset of k0 */
            a[ks][0] = *(const uint32_t*)(smem + SA_OFF + r0 * 144 + kb);
            a[ks][1] = *(const uint32_t*)(smem + SA_OFF + (r0 + 8) * 144 + kb);
            a[ks][2] = *(const uint32_t*)(smem + SA_OFF + r0 * 144 + kb + 16);
            a[ks][3] = *(const uint32_t*)(smem + SA_OFF + (r0 + 8) * 144 + kb + 16);
        }
    }

    float* stg = (float*)(smem + SC_OFF);                  /* [256 b][132 j] */
    for (int bt = bth * 16; bt < bth * 16 + 16; bt++) {
        int bB = bt * 8 + gid;                             /* B-frag column  */
        float c0 = 0.f, c1 = 0.f, c2 = 0.f, c3 = 0.f;
        const char* bh = smem + SBH_OFF + bB * 144;
        const char* bl = smem + SBL_OFF + bB * 144;
#pragma unroll
        for (int ks = 0; ks < 4; ks++) {
            int kb = (ks * 16 + tq * 2) * 2;
            uint32_t b0 = *(const uint32_t*)(bh + kb);
            uint32_t b1 = *(const uint32_t*)(bh + kb + 16);
            mma_bf16(c0, c1, c2, c3, a[ks][0], a[ks][1], a[ks][2], a[ks][3], b0, b1);
            b0 = *(const uint32_t*)(bl + kb);
            b1 = *(const uint32_t*)(bl + kb + 16);
            mma_bf16(c0, c1, c2, c3, a[ks][0], a[ks][1], a[ks][2], a[ks][3], b0, b1);
        }
        int jc = jw * 16 + gid;                            /* C row -> j     */
        int bc = bt * 8 + tq * 2;                          /* C col -> b     */
        stg[bc * 132 + jc]           = c0;
        stg[(bc + 1) * 132 + jc]     = c1;
        stg[bc * 132 + jc + 8]       = c2;
        stg[(bc + 1) * 132 + jc + 8] = c3;
    }
    __syncthreads();

    /* coalesced write-out: 256 b rows x 32 float4 */
    for (int idx = tid; idx < 256 * 32; idx += GTHREADS) {
        int b = idx >> 5, jj = idx & 31;
        int j = jbase + jj * 4;
        if (j < NDATA) {
            float4 v = *(const float4*)(stg + b * 132 + jj * 4);
            *(float4*)(g_sim + (size_t)b * NDATA + j) = v;
        }
    }
}

/* --------------- K3: per-sample 4096-bin histogram of sim ---------------- */
__global__ void k_hist() {
    __shared__ unsigned int sh[NBINS];
    int b = blockIdx.y, tid = threadIdx.x;             /* 256 threads */
    for (int i = tid; i < NBINS; i += 256) sh[i] = 0u;
    __syncthreads();
    size_t base = (size_t)b * NDATA;
    int j0 = blockIdx.x * HCHUNK;
    for (int j = j0 + tid * 4; j < j0 + HCHUNK; j += 256 * 4) {
        float4 s4 = *(const float4*)&g_sim[base + j];
        atomicAdd(&sh[f2u(s4.x) >> 20], 1u);
        atomicAdd(&sh[f2u(s4.y) >> 20], 1u);
        atomicAdd(&sh[f2u(s4.z) >> 20], 1u);
        atomicAdd(&sh[f2u(s4.w) >> 20], 1u);
    }
    __syncthreads();
    for (int i = tid; i < NBINS; i += 256) {
        unsigned int c = sh[i];
        if (c) atomicAdd(&g_hist[b * NBINS + i], c);
    }
}

/* --------- K4: prefix over bins; find bins holding the two ranks --------- */
__global__ void k_scan() {
    int b = blockIdx.x, tid = threadIdx.x;             /* 256 threads x 16 bins */
    __shared__ unsigned int part[256], pref[256];
    unsigned int s = 0;
    for (int i = 0; i < 16; i++) s += g_hist[b * NBINS + tid * 16 + i];
    part[tid] = s;
    __syncthreads();
    if (tid == 0) { unsigned int c = 0; for (int i = 0; i < 256; i++) { pref[i] = c; c += part[i]; } }
    __syncthreads();
    unsigned int c = pref[tid];
    for (int i = 0; i < 16; i++) {
        unsigned int cnt = g_hist[b * NBINS + tid * 16 + i];
        unsigned int nc = c + cnt;
        if (c <= (unsigned)RANK_KTH && (unsigned)RANK_KTH < nc) {
            g_binK[b] = tid * 16 + i; g_resK[b] = RANK_KTH - (int)c;
        }
        if (c <= (unsigned)RANK_TOP && (unsigned)RANK_TOP < nc) g_binT[b] = tid * 16 + i;
        c = nc;
    }
}

/* -------- K5: compact boundary bin, top tail, prefiltered neg keys ------- */
__global__ void k_compact(const float* __restrict__ ru) {
    int b = blockIdx.y;
    int binK = g_binK[b], binT = g_binT[b];
    size_t base = (size_t)b * NDATA;
    int j0 = blockIdx.x * HCHUNK;
    for (int j = j0 + threadIdx.x * 4; j < j0 + HCHUNK; j += 256 * 4) {
        float4 s4 = *(const float4*)&g_sim[base + j];
        float4 r4 = *(const float4*)&ru[base + j];
        float sv[4] = {s4.x, s4.y, s4.z, s4.w};
        float rv[4] = {r4.x, r4.y, r4.z, r4.w};
#pragma unroll
        for (int t = 0; t < 4; t++) {
            unsigned int u = f2u(sv[t]);
            int bin = (int)(u >> 20);
            if (bin >= binK) {
                if (bin == binK) {
                    int id = atomicAdd(&g_cntK[b], 1);
                    if (id < BUFK_CAP) g_bufK[b * BUFK_CAP + id] = u;
                }
                if (bin >= binT) {
                    int id = atomicAdd(&g_cntT[b], 1);
                    if (id < BUFT_CAP) { g_bufTv[b * BUFT_CAP + id] = sv[t]; g_bufTj[b * BUFT_CAP + id] = j + t; }
                }
            }
            if (rv[t] >= PRE_KEY) {
                int id = atomicAdd(&g_cntNeg[b], 1);
                if (id < NEG_CAP) {
                    g_negKey[b * NEG_CAP + id] = __float_as_uint(rv[t]);
                    g_negJ[b * NEG_CAP + id] = j + t;
                }
            }
        }
    }
}

/* -------------- K6: exact kth value via 4-bit radix refine --------------- */
__global__ void k_selectK() {
    int b = blockIdx.x, tid = threadIdx.x;             /* 256 threads */
    __shared__ int h16[16];
    __shared__ unsigned s_pref;
    __shared__ int s_rank;
    int n = min(g_cntK[b], BUFK_CAP);
    if (tid == 0) { s_pref = (unsigned)g_binK[b] << 20; s_rank = g_resK[b]; }
    __syncthreads();
    unsigned pmask = 0xFFF00000u;
    for (int shift = 16; shift >= 0; shift -= 4) {
        if (tid < 16) h16[tid] = 0;
        __syncthreads();
        unsigned pref = s_pref;
        for (int i = tid; i < n; i += 256) {
            unsigned u = g_bufK[b * BUFK_CAP + i];
            if ((u & pmask) == pref) atomicAdd(&h16[(u >> shift) & 15], 1);
        }
        __syncthreads();
        if (tid == 0) {
            int r = s_rank, cum = 0, d = 0;
            for (; d < 16; d++) { int c = h16[d]; if (r < cum + c) { s_rank = r - cum; break; } cum += c; }
            s_pref = pref | ((unsigned)d << shift);
        }
        pmask |= (15u << shift);
        __syncthreads();
    }
    if (tid == 0) g_kthu[b] = s_pref;
}

/* ----- K7: exact top-20 (JAX tie order: value desc, index asc) ----------- */
__global__ void k_selectT() {
    int b = blockIdx.x, lane = threadIdx.x;            /* 32 threads */
    int m = min(g_cntT[b], BUFT_CAP);
    unsigned long long prev = 0xFFFFFFFFFFFFFFFFull;
    for (int it = 0; it < TOPF; it++) {
        unsigned long long best = 0ull;
        for (int i = lane; i < m; i += 32) {
            unsigned long long K = ((unsigned long long)f2u(g_bufTv[b * BUFT_CAP + i]) << 32)
                                 | (unsigned)(~(unsigned)g_bufTj[b * BUFT_CAP + i]);
            if (K < prev && K > best) best = K;
        }
        for (int o = 16; o; o >>= 1) {
            unsigned long long other = __shfl_down_sync(0xffffffffu, best, o);
            if (other > best) best = other;
        }
        best = __shfl_sync(0xffffffffu, best, 0);
        if (lane == 0) {
            g_topv[b * TOPF + it] = u2f((unsigned)(best >> 32));
            g_topi[b * TOPF + it] = (int)(~((unsigned)(best & 0xffffffffu)));
        }
        prev = best;
    }
}

/* ---- K8: filter negs, exact 2500-th key theta, Sum exp, fnp/pos, loss --- */
__global__ void k_neg(const float* __restrict__ memory, const int* __restrict__ bidx) {
    int b = blockIdx.x, tid = threadIdx.x;             /* 256 threads */
    __shared__ float s_f1[BITW];
    __shared__ int s_topi[TOPF], s_valid[TOPF];
    __shared__ float s_topv[TOPF];
    __shared__ int s_pos, s_m2, s_rank, h16[16];
    __shared__ unsigned s_kthu;
    __shared__ unsigned long long s_pref;
    __shared__ float red[256];

    if (tid < BITW) s_f1[tid] = g_f1[b * BITW + tid];
    if (tid == 0) { s_pos = bidx[b]; s_kthu = g_kthu[b]; s_m2 = 0; }
    if (tid < TOPF) { s_topi[tid] = g_topi[b * TOPF + tid]; s_topv[tid] = g_topv[b * TOPF + tid]; }
    __syncthreads();
    if (tid < TOPF) s_valid[tid] = (s_topv[tid] > THRESH && s_topi[tid] != s_pos) ? 1 : 0;
    __syncthreads();
    int pos = s_pos;
    unsigned kthu = s_kthu;

    /* filter + compact surviving 64-bit keys */
    int m = min(g_cntNeg[b], NEG_CAP);
    unsigned long long* K2 = &g_negK2[(size_t)b * NEG_CAP];
    for (int i = tid; i < m; i += 256) {
        int j = g_negJ[b * NEG_CAP + i];
        unsigned keyu = g_negKey[b * NEG_CAP + i];
        if (f2u(g_sim[(size_t)b * NDATA + j]) < kthu) continue;
        if (j == pos) continue;
        bool ex = false;
#pragma unroll
        for (int t = 0; t < TOPF; t++) if (s_valid[t] && s_topi[t] == j) ex = true;
        if (ex) continue;
        int id = atomicAdd(&s_m2, 1);
        K2[id] = ((unsigned long long)keyu << 32) | (unsigned)(~(unsigned)j);
    }
    __syncthreads();
    int m2 = s_m2;

    /* radix-select theta = ascending rank (m2 - KNEG)  == 2500th largest key */
    if (tid == 0) { s_rank = m2 - KNEG; s_pref = 0ull; }
    __syncthreads();
    unsigned long long pmask = 0ull;
    for (int shift = 60; shift >= 0; shift -= 4) {
        if (tid < 16) h16[tid] = 0;
        __syncthreads();
        unsigned long long pref = s_pref;
        for (int i = tid; i < m2; i += 256) {
            unsigned long long K = K2[i];
            if ((K & pmask) == pref) atomicAdd(&h16[(int)((K >> shift) & 15)], 1);
        }
        __syncthreads();
        if (tid == 0) {
            int r = s_rank, cum = 0, d = 0;
            for (; d < 16; d++) { int c = h16[d]; if (r < cum + c) { s_rank = r - cum; break; } cum += c; }
            s_pref = pref | ((unsigned long long)d << shift);
        }
        pmask |= (15ull << shift);
        __syncthreads();
    }
    unsigned long long theta = s_pref;

    /* sum exp(sign(memory[j]) . f1 / T) over selected negatives */
    float acc = 0.f;
    const float scale = 8.0f / TVAL;
    for (int i = tid; i < m2; i += 256) {
        unsigned long long K = K2[i];
        if (K >= theta) {
            int j = (int)(~((unsigned)(K & 0xffffffffu)));
            const float4* mp = (const float4*)(memory + (size_t)j * BITW);
            float d = 0.f;
#pragma unroll
            for (int q = 0; q < 16; q++) {
                float4 t = mp[q];
                d += t.x * s_f1[4*q] + t.y * s_f1[4*q+1] + t.z * s_f1[4*q+2] + t.w * s_f1[4*q+3];
            }
            acc += expf(d * scale);
        }
    }
    red[tid] = acc;
    __syncthreads();
    for (int s = 128; s > 0; s >>= 1) { if (tid < s) red[tid] += red[tid + s]; __syncthreads(); }

    if (tid == 0) {
        float negsum = red[0];
        const float* mpos = memory + (size_t)pos * BITW;
        float dp = 0.f;
        for (int q = 0; q < BITW; q++) dp += mpos[q] * s_f1[q];
        float pos_sim = dp * scale;
        float pe = expf(pos_sim);
        float numer = pe, nf = 0.f;
        for (int t = 0; t < TOPF; t++) {
            if (s_valid[t]) {
                const float* mr = memory + (size_t)s_topi[t] * BITW;
                float d = 0.f;
                for (int q = 0; q < BITW; q++) d += mr[q] * s_f1[q];
                float fs = d * scale;
                numer += fs * expf(fs);
                nf += 1.f;
            }
        }
        float den = negsum + pe;
        g_loss[b] = -logf(numer / den) / (1.f + nf);
    }
}

/* ---- K9: memory -> out copy (dst is out+1: 4B-aligned, scalar stores) --- */
__global__ void k_copy(const float* __restrict__ memory, float* __restrict__ outmem) {
    int n4 = NDATA * BITW / 4;
    int stride = gridDim.x * blockDim.x;
    for (int i = blockIdx.x * blockDim.x + threadIdx.x; i < n4; i += stride) {
        float4 v = *(const float4*)(memory + (size_t)i * 4);
        size_t o = (size_t)i * 4;
        outmem[o]     = v.x;
        outmem[o + 1] = v.y;
        outmem[o + 2] = v.z;
        outmem[o + 3] = v.w;
    }
}

/* -------- K10: momentum update scatter (last-write-wins on dups) --------- */
__global__ void k_update(const float* __restrict__ memory, const int* __restrict__ bidx,
                         float* __restrict__ outmem) {
    int b = blockIdx.x, k = threadIdx.x;               /* 64 threads */
    __shared__ int skip;
    __shared__ float s[BITW];
    __shared__ float nrm;
    if (k == 0) {
        skip = 0;
        int p = bidx[b];
        for (int bb = b + 1; bb < B_SZ; bb++) if (bidx[bb] == p) { skip = 1; break; }
    }
    __syncthreads();
    if (skip) return;
    int p = bidx[b];
    float v = memory[(size_t)p * BITW + k] * 0.4f + g_newf[b * BITW + k] * 0.6f;
    s[k] = v * v;
    __syncthreads();
    if (k == 0) { float t = 0.f; for (int i = 0; i < BITW; i++) t += s[i]; nrm = sqrtf(t); }
    __syncthreads();
    outmem[(size_t)p * BITW + k] = v / nrm;
}

/* -------------------------- K11: mean loss ------------------------------- */
__global__ void k_loss(float* __restrict__ out) {
    __shared__ float r[256];
    int tid = threadIdx.x;
    r[tid] = g_loss[tid];
    __syncthreads();
    for (int s = 128; s > 0; s >>= 1) { if (tid < s) r[tid] += r[tid + s]; __syncthreads(); }
    if (tid == 0) out[0] = r[0] * (1.0f / B_SZ);
}

/* ------------------------------------------------------------------------- */
extern "C" void kernel_launch(void* const* d_in, const int* in_sizes, int n_in,
                              void* d_out, int out_size) {
    const float* iA     = (const float*)d_in[0];
    const float* iB     = (const float*)d_in[1];
    const float* tA     = (const float*)d_in[2];
    const float* tB     = (const float*)d_in[3];
    const float* memory = (const float*)d_in[4];
    const float* ru     = (const float*)d_in[5];
    const int*   bidx   = (const int*)d_in[6];
    float* out = (float*)d_out;

    cudaFuncSetAttribute(k_gemm_mma, cudaFuncAttributeMaxDynamicSharedMemorySize, SMEM_MMA_TOTAL);

    /* k_copy moved to slot 3 so ncu's fixed capture index (4th of ours)
       lands on k_gemm_mma next profile. k_copy only needs `memory` and must
       precede k_update — both hold. */
    k_zero<<<1024, 256>>>();
    k_prep<<<B_SZ, BITW>>>(iA, iB, tA, tB);
    k_copy<<<2048, 256>>>(memory, out + 1);
    k_gemm_mma<<<NJB, GTHREADS, SMEM_MMA_TOTAL>>>(memory);
    k_hist<<<dim3(NDATA / HCHUNK, B_SZ), 256>>>();
    k_scan<<<B_SZ, 256>>>();
    k_compact<<<dim3(NDATA / HCHUNK, B_SZ), 256>>>(ru);
    k_selectK<<<B_SZ, 256>>>();
    k_selectT<<<B_SZ, 32>>>();
    k_neg<<<B_SZ, 256>>>(memory, bidx);
    k_update<<<B_SZ, BITW>>>(memory, bidx, out + 1);
    k_loss<<<1, 256>>>(out);
}

// round 13
// speedup vs baseline: 1.1199x; 1.0186x over previous
#include <cuda_runtime.h>
#include <cuda_bf16.h>
#include <cstdint>

#define B_SZ    256
#define NDATA   200000
#define BITW    64
#define TOPF    20
#define KNEG    2500
#define RANK_KTH 20000          /* N - HIGH : ascending 0-indexed rank of kth   */
#define RANK_TOP 199980         /* N - TOPF : ascending rank of 20th largest    */
#define THRESH  0.3f
#define TVAL    7.2f            /* 0.9*sqrt(64) */
#define PRE_KEY 0.975f
#define NBINS   4096
#define HCHUNK  25000
#define BUFK_CAP 16384
#define BUFT_CAP 8192
#define NEG_CAP  8192

/* ------------- static device scratch (no runtime allocation) ------------- */
__device__ __align__(16) float g_sim[(size_t)B_SZ * NDATA];
__device__ __align__(16) float g_fsum[B_SZ * BITW];
__device__ __align__(16) float g_f1[B_SZ * BITW];
__device__ __align__(16) float g_newf[B_SZ * BITW];
__device__ __align__(16) __nv_bfloat16 g_fh[B_SZ * BITW];
__device__ __align__(16) __nv_bfloat16 g_fl[B_SZ * BITW];
__device__ unsigned int g_hist[B_SZ * NBINS];
__device__ int          g_binK[B_SZ], g_resK[B_SZ], g_binT[B_SZ];
__device__ unsigned int g_kthu[B_SZ];
__device__ unsigned int g_bufK[B_SZ * BUFK_CAP];
__device__ float        g_bufTv[B_SZ * BUFT_CAP];
__device__ int          g_bufTj[B_SZ * BUFT_CAP];
__device__ unsigned int g_negKey[B_SZ * NEG_CAP];
__device__ int          g_negJ[B_SZ * NEG_CAP];
__device__ int          g_cntK[B_SZ], g_cntT[B_SZ], g_cntNeg[B_SZ];
__device__ unsigned long long g_negK2[(size_t)B_SZ * NEG_CAP];
__device__ int          g_topi[B_SZ * TOPF];
__device__ float        g_topv[B_SZ * TOPF];
__device__ float        g_loss[B_SZ];

/* float -> order-preserving uint */
__device__ __forceinline__ unsigned int f2u(float f) {
    unsigned int u = __float_as_uint(f);
    return (u & 0x80000000u) ? ~u : (u | 0x80000000u);
}
__device__ __forceinline__ float u2f(unsigned int x) {
    unsigned int u = (x & 0x80000000u) ? (x ^ 0x80000000u) : ~x;
    return __uint_as_float(u);
}

/* ------------------------- K0: zero counters/hist ------------------------- */
__global__ void k_zero() {
    int i = blockIdx.x * blockDim.x + threadIdx.x;
    int stride = gridDim.x * blockDim.x;
    for (int x = i; x < B_SZ * NBINS; x += stride) g_hist[x] = 0u;
    if (i < B_SZ) { g_cntK[i] = 0; g_cntT[i] = 0; g_cntNeg[i] = 0; }
}

/* --------------- K1: fusions, norms, fsum (+bf16 hi/lo), f1 -------------- */
__global__ void k_prep(const float* __restrict__ iA, const float* __restrict__ iB,
                       const float* __restrict__ tA, const float* __restrict__ tB) {
    int b = blockIdx.x, k = threadIdx.x;               /* 64 threads */
    float ia = iA[b * BITW + k], ib = iB[b * BITW + k];
    float ta = tA[b * BITW + k], tb = tB[b * BITW + k];
    float f1 = (ia + ta) * 0.5f, f2 = (ia + tb) * 0.5f;
    float f3 = (ib + ta) * 0.5f, f4 = (ib + tb) * 0.5f;
    __shared__ float s[4][BITW];
    __shared__ float n[4];
    s[0][k] = f1 * f1; s[1][k] = f2 * f2; s[2][k] = f3 * f3; s[3][k] = f4 * f4;
    __syncthreads();
    if (k < 4) { float t = 0.f; for (int i = 0; i < BITW; i++) t += s[k][i]; n[k] = sqrtf(t); }
    __syncthreads();
    float fs = 0.25f * (f1 / n[0] + f2 / n[1] + f3 / n[2] + f4 / n[3]);
    g_fsum[b * BITW + k] = fs;
    __nv_bfloat16 h = __float2bfloat16_rn(fs);
    g_fh[b * BITW + k] = h;
    g_fl[b * BITW + k] = __float2bfloat16_rn(fs - __bfloat162float(h));
    g_f1[b * BITW + k]   = f1;
    g_newf[b * BITW + k] = f1 / n[0];
}

/* ---------- K2: sim = fsum @ memory^T via mma.sync bf16 (hi/lo) ----------
 * CTA: 128 j x 256 b. 512 threads / 16 warps: warp w -> j rows (w&7)*16..+15,
 * bt range (w>>3)*16..+15. A = memory bf16 (EXACT: +-1/8). B = fsum hi/lo.
 * smem: A[128 x 144B] | Bh[256 x 144B] | Bl[256 x 144B] | stage[256 x 132 f32]
 * Row strides chosen for conflict-free fragment LDS / staging STS.          */
#define SA_OFF   0
#define SBH_OFF  18432                      /* 128*144 */
#define SBL_OFF  (18432 + 36864)            /* +256*144 */
#define SC_OFF   (18432 + 36864 + 36864)
#define SMEM_MMA_TOTAL (18432 + 36864 + 36864 + 256 * 132 * 4)  /* 227328 */
#define NJB ((NDATA + 127) / 128)
#define GTHREADS 512

__device__ __forceinline__ void mma_bf16(float& c0, float& c1, float& c2, float& c3,
                                         uint32_t a0, uint32_t a1, uint32_t a2, uint32_t a3,
                                         uint32_t b0, uint32_t b1) {
    asm volatile("mma.sync.aligned.m16n8k16.row.col.f32.bf16.bf16.f32 "
                 "{%0,%1,%2,%3}, {%4,%5,%6,%7}, {%8,%9}, {%0,%1,%2,%3};"
                 : "+f"(c0), "+f"(c1), "+f"(c2), "+f"(c3)
                 : "r"(a0), "r"(a1), "r"(a2), "r"(a3), "r"(b0), "r"(b1));
}

__global__ void __launch_bounds__(GTHREADS) k_gemm_mma(const float* __restrict__ memory) {
    extern __shared__ char smem[];
    int tid = threadIdx.x, wid = tid >> 5, t = tid & 31;
    int gid = t >> 2, tq = t & 3;
    int jw = wid & 7, bth = wid >> 3;                  /* j-row set, bt half */
    int jbase = blockIdx.x * 128;

    /* A: 128 rows x 32 bf16-pairs; convert fp32 -> bf16 (exact for +-1/8) */
    for (int idx = tid; idx < 128 * 32; idx += GTHREADS) {
        int row = idx >> 5, pr = idx & 31;
        int j = jbase + row;
        uint32_t pk = 0u;
        if (j < NDATA) {
            float2 v = *(const float2*)(memory + (size_t)j * BITW + pr * 2);
            pk = ((uint32_t)__bfloat16_as_ushort(__float2bfloat16_rn(v.y)) << 16)
               |  (uint32_t)__bfloat16_as_ushort(__float2bfloat16_rn(v.x));
        }
        *(uint32_t*)(smem + SA_OFF + row * 144 + pr * 4) = pk;
    }
    /* B hi/lo: restride 64 bf16 rows -> 144B rows */
    for (int idx = tid; idx < 256 * 32; idx += GTHREADS) {
        int b = idx >> 5, pr = idx & 31;
        *(uint32_t*)(smem + SBH_OFF + b * 144 + pr * 4) = ((const uint32_t*)g_fh)[b * 32 + pr];
        *(uint32_t*)(smem + SBL_OFF + b * 144 + pr * 4) = ((const uint32_t*)g_fl)[b * 32 + pr];
    }
    __syncthreads();

    /* A fragments for this warp's 16 j rows (rows jw*16 + gid, +8) */
    uint32_t a[4][4];
    {
        int r0 = jw * 16 + gid;
#pragma unroll
        for (int ks = 0; ks < 4; ks++) {
            int kb = (ks * 16 + tq * 2) * 2;               /* byte offset of k0 */
            a[ks][0] = *(const uint32_t*)(smem + SA_OFF + r0 * 144 + kb);
            a[ks][1] = *(const uint32_t*)(smem + SA_OFF + (r0 + 8) * 144 + kb);
            a[ks][2] = *(const uint32_t*)(smem + SA_OFF + r0 * 144 + kb + 16);
            a[ks][3] = *(const uint32_t*)(smem + SA_OFF + (r0 + 8) * 144 + kb + 16);
        }
    }

    float* stg = (float*)(smem + SC_OFF);                  /* [256 b][132 j] */
    for (int bt = bth * 16; bt < bth * 16 + 16; bt++) {
        int bB = bt * 8 + gid;                             /* B-frag column  */
        float c0 = 0.f, c1 = 0.f, c2 = 0.f, c3 = 0.f;
        const char* bh = smem + SBH_OFF + bB * 144;
        const char* bl = smem + SBL_OFF + bB * 144;
#pragma unroll
        for (int ks = 0; ks < 4; ks++) {
            int kb = (ks * 16 + tq * 2) * 2;
            uint32_t b0 = *(const uint32_t*)(bh + kb);
            uint32_t b1 = *(const uint32_t*)(bh + kb + 16);
            mma_bf16(c0, c1, c2, c3, a[ks][0], a[ks][1], a[ks][2], a[ks][3], b0, b1);
            b0 = *(const uint32_t*)(bl + kb);
            b1 = *(const uint32_t*)(bl + kb + 16);
            mma_bf16(c0, c1, c2, c3, a[ks][0], a[ks][1], a[ks][2], a[ks][3], b0, b1);
        }
        int jc = jw * 16 + gid;                            /* C row -> j     */
        int bc = bt * 8 + tq * 2;                          /* C col -> b     */
        stg[bc * 132 + jc]           = c0;
        stg[(bc + 1) * 132 + jc]     = c1;
        stg[bc * 132 + jc + 8]       = c2;
        stg[(bc + 1) * 132 + jc + 8] = c3;
    }
    __syncthreads();

    /* coalesced write-out: 256 b rows x 32 float4 */
    for (int idx = tid; idx < 256 * 32; idx += GTHREADS) {
        int b = idx >> 5, jj = idx & 31;
        int j = jbase + jj * 4;
        if (j < NDATA) {
            float4 v = *(const float4*)(stg + b * 132 + jj * 4);
            *(float4*)(g_sim + (size_t)b * NDATA + j) = v;
        }
    }
}

/* --------------- K3: per-sample 4096-bin histogram of sim ---------------- */
__global__ void k_hist() {
    __shared__ unsigned int sh[NBINS];
    int b = blockIdx.y, tid = threadIdx.x;             /* 256 threads */
    for (int i = tid; i < NBINS; i += 256) sh[i] = 0u;
    __syncthreads();
    size_t base = (size_t)b * NDATA;
    int j0 = blockIdx.x * HCHUNK;
    for (int j = j0 + tid * 4; j < j0 + HCHUNK; j += 256 * 4) {
        float4 s4 = *(const float4*)&g_sim[base + j];
        atomicAdd(&sh[f2u(s4.x) >> 20], 1u);
        atomicAdd(&sh[f2u(s4.y) >> 20], 1u);
        atomicAdd(&sh[f2u(s4.z) >> 20], 1u);
        atomicAdd(&sh[f2u(s4.w) >> 20], 1u);
    }
    __syncthreads();
    for (int i = tid; i < NBINS; i += 256) {
        unsigned int c = sh[i];
        if (c) atomicAdd(&g_hist[b * NBINS + i], c);
    }
}

/* --------- K4: prefix over bins; find bins holding the two ranks --------- */
__global__ void k_scan() {
    int b = blockIdx.x, tid = threadIdx.x;             /* 256 threads x 16 bins */
    __shared__ unsigned int part[256], pref[256];
    unsigned int s = 0;
    for (int i = 0; i < 16; i++) s += g_hist[b * NBINS + tid * 16 + i];
    part[tid] = s;
    __syncthreads();
    if (tid == 0) { unsigned int c = 0; for (int i = 0; i < 256; i++) { pref[i] = c; c += part[i]; } }
    __syncthreads();
    unsigned int c = pref[tid];
    for (int i = 0; i < 16; i++) {
        unsigned int cnt = g_hist[b * NBINS + tid * 16 + i];
        unsigned int nc = c + cnt;
        if (c <= (unsigned)RANK_KTH && (unsigned)RANK_KTH < nc) {
            g_binK[b] = tid * 16 + i; g_resK[b] = RANK_KTH - (int)c;
        }
        if (c <= (unsigned)RANK_TOP && (unsigned)RANK_TOP < nc) g_binT[b] = tid * 16 + i;
        c = nc;
    }
}

/* -------- K5: compact boundary bin, top tail, prefiltered neg keys ------- */
__global__ void k_compact(const float* __restrict__ ru) {
    int b = blockIdx.y;
    int binK = g_binK[b], binT = g_binT[b];
    size_t base = (size_t)b * NDATA;
    int j0 = blockIdx.x * HCHUNK;
    for (int j = j0 + threadIdx.x * 4; j < j0 + HCHUNK; j += 256 * 4) {
        float4 s4 = *(const float4*)&g_sim[base + j];
        float4 r4 = *(const float4*)&ru[base + j];
        float sv[4] = {s4.x, s4.y, s4.z, s4.w};
        float rv[4] = {r4.x, r4.y, r4.z, r4.w};
#pragma unroll
        for (int t = 0; t < 4; t++) {
            unsigned int u = f2u(sv[t]);
            int bin = (int)(u >> 20);
            if (bin >= binK) {
                if (bin == binK) {
                    int id = atomicAdd(&g_cntK[b], 1);
                    if (id < BUFK_CAP) g_bufK[b * BUFK_CAP + id] = u;
                }
                if (bin >= binT) {
                    int id = atomicAdd(&g_cntT[b], 1);
                    if (id < BUFT_CAP) { g_bufTv[b * BUFT_CAP + id] = sv[t]; g_bufTj[b * BUFT_CAP + id] = j + t; }
                }
            }
            if (rv[t] >= PRE_KEY) {
                int id = atomicAdd(&g_cntNeg[b], 1);
                if (id < NEG_CAP) {
                    g_negKey[b * NEG_CAP + id] = __float_as_uint(rv[t]);
                    g_negJ[b * NEG_CAP + id] = j + t;
                }
            }
        }
    }
}

/* -------------- K6: exact kth value via 4-bit radix refine --------------- */
__global__ void k_selectK() {
    int b = blockIdx.x, tid = threadIdx.x;             /* 256 threads */
    __shared__ int h16[16];
    __shared__ unsigned s_pref;
    __shared__ int s_rank;
    int n = min(g_cntK[b], BUFK_CAP);
    if (tid == 0) { s_pref = (unsigned)g_binK[b] << 20; s_rank = g_resK[b]; }
    __syncthreads();
    unsigned pmask = 0xFFF00000u;
    for (int shift = 16; shift >= 0; shift -= 4) {
        if (tid < 16) h16[tid] = 0;
        __syncthreads();
        unsigned pref = s_pref;
        for (int i = tid; i < n; i += 256) {
            unsigned u = g_bufK[b * BUFK_CAP + i];
            if ((u & pmask) == pref) atomicAdd(&h16[(u >> shift) & 15], 1);
        }
        __syncthreads();
        if (tid == 0) {
            int r = s_rank, cum = 0, d = 0;
            for (; d < 16; d++) { int c = h16[d]; if (r < cum + c) { s_rank = r - cum; break; } cum += c; }
            s_pref = pref | ((unsigned)d << shift);
        }
        pmask |= (15u << shift);
        __syncthreads();
    }
    if (tid == 0) g_kthu[b] = s_pref;
}

/* ----- K7: exact top-20 (JAX tie order: value desc, index asc) ----------- */
__global__ void k_selectT() {
    int b = blockIdx.x, lane = threadIdx.x;            /* 32 threads */
    int m = min(g_cntT[b], BUFT_CAP);
    unsigned long long prev = 0xFFFFFFFFFFFFFFFFull;
    for (int it = 0; it < TOPF; it++) {
        unsigned long long best = 0ull;
        for (int i = lane; i < m; i += 32) {
            unsigned long long K = ((unsigned long long)f2u(g_bufTv[b * BUFT_CAP + i]) << 32)
                                 | (unsigned)(~(unsigned)g_bufTj[b * BUFT_CAP + i]);
            if (K < prev && K > best) best = K;
        }
        for (int o = 16; o; o >>= 1) {
            unsigned long long other = __shfl_down_sync(0xffffffffu, best, o);
            if (other > best) best = other;
        }
        best = __shfl_sync(0xffffffffu, best, 0);
        if (lane == 0) {
            g_topv[b * TOPF + it] = u2f((unsigned)(best >> 32));
            g_topi[b * TOPF + it] = (int)(~((unsigned)(best & 0xffffffffu)));
        }
        prev = best;
    }
}

/* ---- K8: filter negs, exact 2500-th key theta, Sum exp, fnp/pos, loss --- */
__global__ void k_neg(const float* __restrict__ memory, const int* __restrict__ bidx) {
    int b = blockIdx.x, tid = threadIdx.x;             /* 256 threads */
    __shared__ float s_f1[BITW];
    __shared__ int s_topi[TOPF], s_valid[TOPF];
    __shared__ float s_topv[TOPF];
    __shared__ int s_pos, s_m2, s_rank, h16[16];
    __shared__ unsigned s_kthu;
    __shared__ unsigned long long s_pref;
    __shared__ float red[256];

    if (tid < BITW) s_f1[tid] = g_f1[b * BITW + tid];
    if (tid == 0) { s_pos = bidx[b]; s_kthu = g_kthu[b]; s_m2 = 0; }
    if (tid < TOPF) { s_topi[tid] = g_topi[b * TOPF + tid]; s_topv[tid] = g_topv[b * TOPF + tid]; }
    __syncthreads();
    if (tid < TOPF) s_valid[tid] = (s_topv[tid] > THRESH && s_topi[tid] != s_pos) ? 1 : 0;
    __syncthreads();
    int pos = s_pos;
    unsigned kthu = s_kthu;

    /* filter + compact surviving 64-bit keys */
    int m = min(g_cntNeg[b], NEG_CAP);
    unsigned long long* K2 = &g_negK2[(size_t)b * NEG_CAP];
    for (int i = tid; i < m; i += 256) {
        int j = g_negJ[b * NEG_CAP + i];
        unsigned keyu = g_negKey[b * NEG_CAP + i];
        if (f2u(g_sim[(size_t)b * NDATA + j]) < kthu) continue;
        if (j == pos) continue;
        bool ex = false;
#pragma unroll
        for (int t = 0; t < TOPF; t++) if (s_valid[t] && s_topi[t] == j) ex = true;
        if (ex) continue;
        int id = atomicAdd(&s_m2, 1);
        K2[id] = ((unsigned long long)keyu << 32) | (unsigned)(~(unsigned)j);
    }
    __syncthreads();
    int m2 = s_m2;

    /* radix-select theta = ascending rank (m2 - KNEG)  == 2500th largest key */
    if (tid == 0) { s_rank = m2 - KNEG; s_pref = 0ull; }
    __syncthreads();
    unsigned long long pmask = 0ull;
    for (int shift = 60; shift >= 0; shift -= 4) {
        if (tid < 16) h16[tid] = 0;
        __syncthreads();
        unsigned long long pref = s_pref;
        for (int i = tid; i < m2; i += 256) {
            unsigned long long K = K2[i];
            if ((K & pmask) == pref) atomicAdd(&h16[(int)((K >> shift) & 15)], 1);
        }
        __syncthreads();
        if (tid == 0) {
            int r = s_rank, cum = 0, d = 0;
            for (; d < 16; d++) { int c = h16[d]; if (r < cum + c) { s_rank = r - cum; break; } cum += c; }
            s_pref = pref | ((unsigned long long)d << shift);
        }
        pmask |= (15ull << shift);
        __syncthreads();
    }
    unsigned long long theta = s_pref;

    /* sum exp(sign(memory[j]) . f1 / T) over selected negatives */
    float acc = 0.f;
    const float scale = 8.0f / TVAL;
    for (int i = tid; i < m2; i += 256) {
        unsigned long long K = K2[i];
        if (K >= theta) {
            int j = (int)(~((unsigned)(K & 0xffffffffu)));
            const float4* mp = (const float4*)(memory + (size_t)j * BITW);
            float d = 0.f;
#pragma unroll
            for (int q = 0; q < 16; q++) {
                float4 t = mp[q];
                d += t.x * s_f1[4*q] + t.y * s_f1[4*q+1] + t.z * s_f1[4*q+2] + t.w * s_f1[4*q+3];
            }
            acc += expf(d * scale);
        }
    }
    red[tid] = acc;
    __syncthreads();
    for (int s = 128; s > 0; s >>= 1) { if (tid < s) red[tid] += red[tid + s]; __syncthreads(); }

    if (tid == 0) {
        float negsum = red[0];
        const float* mpos = memory + (size_t)pos * BITW;
        float dp = 0.f;
        for (int q = 0; q < BITW; q++) dp += mpos[q] * s_f1[q];
        float pos_sim = dp * scale;
        float pe = expf(pos_sim);
        float numer = pe, nf = 0.f;
        for (int t = 0; t < TOPF; t++) {
            if (s_valid[t]) {
                const float* mr = memory + (size_t)s_topi[t] * BITW;
                float d = 0.f;
                for (int q = 0; q < BITW; q++) d += mr[q] * s_f1[q];
                float fs = d * scale;
                numer += fs * expf(fs);
                nf += 1.f;
            }
        }
        float den = negsum + pe;
        g_loss[b] = -logf(numer / den) / (1.f + nf);
    }
}

/* ---- K9: memory -> out copy (dst is out+1: 4B-aligned, scalar stores) --- */
__global__ void k_copy(const float* __restrict__ memory, float* __restrict__ outmem) {
    int n4 = NDATA * BITW / 4;
    int stride = gridDim.x * blockDim.x;
    for (int i = blockIdx.x * blockDim.x + threadIdx.x; i < n4; i += stride) {
        float4 v = *(const float4*)(memory + (size_t)i * 4);
        size_t o = (size_t)i * 4;
        outmem[o]     = v.x;
        outmem[o + 1] = v.y;
        outmem[o + 2] = v.z;
        outmem[o + 3] = v.w;
    }
}

/* -------- K10: momentum update scatter (last-write-wins on dups) --------- */
__global__ void k_update(const float* __restrict__ memory, const int* __restrict__ bidx,
                         float* __restrict__ outmem) {
    int b = blockIdx.x, k = threadIdx.x;               /* 64 threads */
    __shared__ int skip;
    __shared__ float s[BITW];
    __shared__ float nrm;
    if (k == 0) {
        skip = 0;
        int p = bidx[b];
        for (int bb = b + 1; bb < B_SZ; bb++) if (bidx[bb] == p) { skip = 1; break; }
    }
    __syncthreads();
    if (skip) return;
    int p = bidx[b];
    float v = memory[(size_t)p * BITW + k] * 0.4f + g_newf[b * BITW + k] * 0.6f;
    s[k] = v * v;
    __syncthreads();
    if (k == 0) { float t = 0.f; for (int i = 0; i < BITW; i++) t += s[i]; nrm = sqrtf(t); }
    __syncthreads();
    outmem[(size_t)p * BITW + k] = v / nrm;
}

/* -------------------------- K11: mean loss ------------------------------- */
__global__ void k_loss(float* __restrict__ out) {
    __shared__ float r[256];
    int tid = threadIdx.x;
    r[tid] = g_loss[tid];
    __syncthreads();
    for (int s = 128; s > 0; s >>= 1) { if (tid < s) r[tid] += r[tid + s]; __syncthreads(); }
    if (tid == 0) out[0] = r[0] * (1.0f / B_SZ);
}

/* ------------------------------------------------------------------------- */
extern "C" void kernel_launch(void* const* d_in, const int* in_sizes, int n_in,
                              void* d_out, int out_size) {
    const float* iA     = (const float*)d_in[0];
    const float* iB     = (const float*)d_in[1];
    const float* tA     = (const float*)d_in[2];
    const float* tB     = (const float*)d_in[3];
    const float* memory = (const float*)d_in[4];
    const float* ru     = (const float*)d_in[5];
    const int*   bidx   = (const int*)d_in[6];
    float* out = (float*)d_out;

    cudaFuncSetAttribute(k_gemm_mma, cudaFuncAttributeMaxDynamicSharedMemorySize, SMEM_MMA_TOTAL);

    /* k_copy moved to slot 3 so ncu's fixed capture index (4th of ours)
       lands on k_gemm_mma next profile. k_copy only needs `memory` and must
       precede k_update — both hold. */
    k_zero<<<1024, 256>>>();
    k_prep<<<B_SZ, BITW>>>(iA, iB, tA, tB);
    k_copy<<<2048, 256>>>(memory, out + 1);
    k_gemm_mma<<<NJB, GTHREADS, SMEM_MMA_TOTAL>>>(memory);
    k_hist<<<dim3(NDATA / HCHUNK, B_SZ), 256>>>();
    k_scan<<<B_SZ, 256>>>();
    k_compact<<<dim3(NDATA / HCHUNK, B_SZ), 256>>>(ru);
    k_selectK<<<B_SZ, 256>>>();
    k_selectT<<<B_SZ, 32>>>();
    k_neg<<<B_SZ, 256>>>(memory, bidx);
    k_update<<<B_SZ, BITW>>>(memory, bidx, out + 1);
    k_loss<<<1, 256>>>(out);
}